// round 14
// baseline (speedup 1.0000x reference)
#include <cuda_runtime.h>
#include <math.h>

#define NCLS 19
#define DD   128
#define HWP  65536          // H*W
#define BB   8
#define NPIX (BB*HWP)       // 524288

#define P1_BLOCKS  592              // 4 x 148 SMs, single wave
#define P1_THREADS 288              // 8 MMA warps (dims) + 1 label warp
#define P1_CHUNK   128              // pixels per chunk (8 ksteps)
#define P1_NCHUNK  (NPIX/P1_CHUNK)  // 4096

#define P2_BLOCKS  740              // 5 x 148 SMs, single wave
#define P2_THREADS 256              // 128 px-slots x 2 d-halves
#define P2_SLAB    128              // pixels per slab
#define P2_NSLAB   (NPIX/P2_SLAB)   // 4096

// ---- static scratch (no allocations allowed; zero-init at load) ----
__device__ float          g_sums[NCLS*DD];
__device__ int            g_cnt[NCLS];
__device__ float          g_var[NCLS];
__device__ unsigned int   g_done2;
__device__ unsigned char  g_labs[NPIX];

// ---------------------------------------------------------------- pass 1
// Segment-sum as GEMM: D[d][c] = sum_p feats[d][p] * onehot(lab[p]==c).
// Warps 0..7: mma.sync.m16n8k16, A = feats [16 dims x 16 px] bf16 loaded
// straight from global in fragment layout, B = onehot built in registers
// from raw int32 labels, C = fp32 [16 d x 24 cls] accumulated across all
// chunks; single atomic writeout.
// Warp 8: reads raw labels (int4), histograms into g_cnt, packs g_labs.
__global__ void __launch_bounds__(P1_THREADS, 4) k_pass1(const float* __restrict__ feats,
                                                         const int* __restrict__ labels) {
    __shared__ int hist[NCLS];
    int w    = threadIdx.x >> 5;
    int lane = threadIdx.x & 31;

    if (w == 8) {
        // ---------------- label warp: histogram + pack ----------------
        if (lane < NCLS) hist[lane] = 0;
        __syncwarp();
        for (int ch = blockIdx.x; ch < P1_NCHUNK; ch += P1_BLOCKS) {
            int pxg = ch * P1_CHUNK;
            int4 lv = ((const int4*)(labels + pxg))[lane];   // 4 labels/lane
            uchar4 u;
            u.x = (lv.x >= 0 && lv.x < NCLS) ? (unsigned char)lv.x : (unsigned char)255;
            u.y = (lv.y >= 0 && lv.y < NCLS) ? (unsigned char)lv.y : (unsigned char)255;
            u.z = (lv.z >= 0 && lv.z < NCLS) ? (unsigned char)lv.z : (unsigned char)255;
            u.w = (lv.w >= 0 && lv.w < NCLS) ? (unsigned char)lv.w : (unsigned char)255;
            ((uchar4*)(g_labs + pxg))[lane] = u;
            if (u.x < NCLS) atomicAdd(&hist[u.x], 1);
            if (u.y < NCLS) atomicAdd(&hist[u.y], 1);
            if (u.z < NCLS) atomicAdd(&hist[u.z], 1);
            if (u.w < NCLS) atomicAdd(&hist[u.w], 1);
        }
        __syncwarp();
        if (lane < NCLS) atomicAdd(&g_cnt[lane], hist[lane]);
        return;
    }

    // ---------------- MMA warps: segment-sum GEMM ----------------
    int gid  = lane >> 2;            // 0..7
    int ktid = lane & 3;             // 0..3
    int d_lo = w*16 + gid;

    float c0[4] = {0.f,0.f,0.f,0.f};
    float c1[4] = {0.f,0.f,0.f,0.f};
    float c2[4] = {0.f,0.f,0.f,0.f};

    for (int ch = blockIdx.x; ch < P1_NCHUNK; ch += P1_BLOCKS) {
        int pxg = ch * P1_CHUNK;         // plane-aligned: 128 | 65536
        int b   = pxg >> 16;
        int po  = pxg & 65535;
        const float* rowA = feats + ((size_t)b*DD + d_lo    ) * HWP + po;
        const float* rowB = feats + ((size_t)b*DD + d_lo + 8) * HWP + po;
        const int*   labp = labels + pxg;

        #pragma unroll 2
        for (int ks = 0; ks < P1_CHUNK/16; ks++) {
            int p0 = ks*16 + 2*ktid;     // thread's k-anchor within the 16-px tile
            float2 fa0 = *(const float2*)(rowA + p0);        // A[gid][k0,k0+1]
            float2 fa1 = *(const float2*)(rowB + p0);        // A[gid+8][k0,k0+1]
            float2 fa2 = *(const float2*)(rowA + p0 + 8);    // A[gid][k0+8,k0+9]
            float2 fa3 = *(const float2*)(rowB + p0 + 8);    // A[gid+8][k0+8,k0+9]
            unsigned a0, a1, a2, a3;
            asm("cvt.rn.bf16x2.f32 %0, %1, %2;" : "=r"(a0) : "f"(fa0.y), "f"(fa0.x));
            asm("cvt.rn.bf16x2.f32 %0, %1, %2;" : "=r"(a1) : "f"(fa1.y), "f"(fa1.x));
            asm("cvt.rn.bf16x2.f32 %0, %1, %2;" : "=r"(a2) : "f"(fa2.y), "f"(fa2.x));
            asm("cvt.rn.bf16x2.f32 %0, %1, %2;" : "=r"(a3) : "f"(fa3.y), "f"(fa3.x));

            int2 L01 = *(const int2*)(labp + p0);       // L1/L2 hit (8 warps share)
            int2 L89 = *(const int2*)(labp + p0 + 8);
            int l0 = L01.x, l1 = L01.y;
            int l8 = L89.x, l9 = L89.y;

            {   int cls = gid;                       // tile 0: classes 0..7
                unsigned b0 = (l0==cls ? 0x3F80u : 0u) | (l1==cls ? 0x3F800000u : 0u);
                unsigned b1 = (l8==cls ? 0x3F80u : 0u) | (l9==cls ? 0x3F800000u : 0u);
                asm("mma.sync.aligned.m16n8k16.row.col.f32.bf16.bf16.f32 "
                    "{%0,%1,%2,%3}, {%4,%5,%6,%7}, {%8,%9}, {%0,%1,%2,%3};"
                    : "+f"(c0[0]), "+f"(c0[1]), "+f"(c0[2]), "+f"(c0[3])
                    : "r"(a0), "r"(a1), "r"(a2), "r"(a3), "r"(b0), "r"(b1));
            }
            {   int cls = gid + 8;                   // tile 1: classes 8..15
                unsigned b0 = (l0==cls ? 0x3F80u : 0u) | (l1==cls ? 0x3F800000u : 0u);
                unsigned b1 = (l8==cls ? 0x3F80u : 0u) | (l9==cls ? 0x3F800000u : 0u);
                asm("mma.sync.aligned.m16n8k16.row.col.f32.bf16.bf16.f32 "
                    "{%0,%1,%2,%3}, {%4,%5,%6,%7}, {%8,%9}, {%0,%1,%2,%3};"
                    : "+f"(c1[0]), "+f"(c1[1]), "+f"(c1[2]), "+f"(c1[3])
                    : "r"(a0), "r"(a1), "r"(a2), "r"(a3), "r"(b0), "r"(b1));
            }
            {   int cls = gid + 16;                  // tile 2: classes 16..23
                unsigned b0 = (l0==cls ? 0x3F80u : 0u) | (l1==cls ? 0x3F800000u : 0u);
                unsigned b1 = (l8==cls ? 0x3F80u : 0u) | (l9==cls ? 0x3F800000u : 0u);
                asm("mma.sync.aligned.m16n8k16.row.col.f32.bf16.bf16.f32 "
                    "{%0,%1,%2,%3}, {%4,%5,%6,%7}, {%8,%9}, {%0,%1,%2,%3};"
                    : "+f"(c2[0]), "+f"(c2[1]), "+f"(c2[2]), "+f"(c2[3])
                    : "r"(a0), "r"(a1), "r"(a2), "r"(a3), "r"(b0), "r"(b1));
            }
        }
    }

    // writeout: C[m][n] -> d = w*16 + m (m = gid, gid+8), cls = 8t + n
    int dA = w*16 + gid, dB = dA + 8;
    {   int n0 = 2*ktid, n1 = n0 + 1;             // tile 0: cls 0..7
        atomicAdd(&g_sums[n0*DD + dA], c0[0]);
        atomicAdd(&g_sums[n1*DD + dA], c0[1]);
        atomicAdd(&g_sums[n0*DD + dB], c0[2]);
        atomicAdd(&g_sums[n1*DD + dB], c0[3]);
    }
    {   int n0 = 8 + 2*ktid, n1 = n0 + 1;         // tile 1: cls 8..15
        atomicAdd(&g_sums[n0*DD + dA], c1[0]);
        atomicAdd(&g_sums[n1*DD + dA], c1[1]);
        atomicAdd(&g_sums[n0*DD + dB], c1[2]);
        atomicAdd(&g_sums[n1*DD + dB], c1[3]);
    }
    {   int n0 = 16 + 2*ktid, n1 = n0 + 1;        // tile 2: cls 16..23 (keep <19)
        if (n0 < NCLS) { atomicAdd(&g_sums[n0*DD + dA], c2[0]);
                         atomicAdd(&g_sums[n0*DD + dB], c2[2]); }
        if (n1 < NCLS) { atomicAdd(&g_sums[n1*DD + dA], c2[1]);
                         atomicAdd(&g_sums[n1*DD + dB], c2[3]); }
    }
}

// ---------------------------------------------------------------- pass 2
// Pass1-clone configuration: grid 740 (5/SM single wave, 51-reg budget),
// grid-stride over 4096 slabs of 128 px. Thread t owns pixel (t&127) of
// the slab and d-half dh = t>>7; walks 8 iters x 8 concurrent plane loads
// (scalar; warp = 128B contiguous per plane). Per-slab d-half combine via
// shared, then hinge + class atomicAdd. Means in shared at stride 129.
// Last-arriving block assembles the final loss and resets scratch.
__global__ void __launch_bounds__(P2_THREADS, 5) k_pass2(const float* __restrict__ feats,
                                                         float* __restrict__ out) {
    __shared__ float ms[NCLS*129];
    __shared__ float vs[NCLS];
    __shared__ float ps[P2_SLAB];
    int t = threadIdx.x;
    for (int i = t; i < NCLS*DD; i += P2_THREADS) {
        int c = i >> 7;
        ms[c*129 + (i & 127)] = g_sums[i] / fmaxf((float)g_cnt[c], 1.f);
    }
    if (t < NCLS) vs[t] = 0.f;
    __syncthreads();

    int pxl   = t & 127;          // pixel slot within slab
    int dh    = t >> 7;           // 0 or 1
    int dbase = dh * 64;

    for (int sl = blockIdx.x; sl < P2_NSLAB; sl += P2_BLOCKS) {
        int px = sl * P2_SLAB + pxl;      // slab is plane-aligned (128 | 65536)
        int b  = px >> 16;
        int po = px & 65535;
        const float* fb = feats + ((size_t)b*DD + dbase) * HWP + po;

        int lab = g_labs[px];
        const float* mr = ms + (lab < NCLS ? lab : 0)*129 + dbase;

        float acc = 0.f;
        for (int d = 0; d < 8; d++) {
            float v0 = fb[(size_t)(d     )*HWP];
            float v1 = fb[(size_t)(d +  8)*HWP];
            float v2 = fb[(size_t)(d + 16)*HWP];
            float v3 = fb[(size_t)(d + 24)*HWP];
            float v4 = fb[(size_t)(d + 32)*HWP];
            float v5 = fb[(size_t)(d + 40)*HWP];
            float v6 = fb[(size_t)(d + 48)*HWP];
            float v7 = fb[(size_t)(d + 56)*HWP];
            float df;
            df = v0 - mr[d     ]; acc = fmaf(df, df, acc);
            df = v1 - mr[d +  8]; acc = fmaf(df, df, acc);
            df = v2 - mr[d + 16]; acc = fmaf(df, df, acc);
            df = v3 - mr[d + 24]; acc = fmaf(df, df, acc);
            df = v4 - mr[d + 32]; acc = fmaf(df, df, acc);
            df = v5 - mr[d + 40]; acc = fmaf(df, df, acc);
            df = v6 - mr[d + 48]; acc = fmaf(df, df, acc);
            df = v7 - mr[d + 56]; acc = fmaf(df, df, acc);
        }
        if (dh == 1) ps[pxl] = acc;
        __syncthreads();
        if (dh == 0 && lab < NCLS) {
            float tot = acc + ps[pxl];
            float h = fmaxf(sqrtf(tot) - 0.5f, 0.f);   // DELTA_V = 0.5
            atomicAdd(&vs[lab], h*h);
        }
        __syncthreads();                 // ps reusable next slab
    }
    __syncthreads();
    if (t < NCLS) atomicAdd(&g_var[t], vs[t]);

    // ---- last-arriving block: final loss assembly + scratch reset ----
    __threadfence();
    __shared__ bool isLast;
    if (t == 0) isLast = (atomicAdd(&g_done2, 1u) == P2_BLOCKS - 1);
    __syncthreads();
    if (!isLast) return;

    __shared__ float vld[NCLS];
    __shared__ float sreg[NCLS];
    __shared__ float spair[NCLS*NCLS];
    if (t < NCLS) {
        vld[t] = (g_cnt[t] > 100) ? 1.f : 0.f;   // MAX_VIEWS = 100, strict >
        float s = 0.f;
        #pragma unroll 16
        for (int d = 0; d < DD; d++) { float m = ms[t*129 + d]; s = fmaf(m, m, s); }
        sreg[t] = (s > 0.f) ? sqrtf(s) : 0.f;
    }
    for (int idx = t; idx < NCLS*NCLS; idx += P2_THREADS) {
        int a = idx / NCLS, b2 = idx % NCLS;
        float s = 0.f;
        #pragma unroll 16
        for (int d = 0; d < DD; d++) {
            float diff = ms[a*129 + d] - ms[b2*129 + d];
            s = fmaf(diff, diff, s);
        }
        float pdn = (s > 0.f) ? sqrtf(s) : 0.f;
        float hd  = fmaxf(2.f*1.5f - pdn, 0.f);   // 2*DELTA_D
        spair[idx] = hd*hd;
    }
    // reset g_sums for next replay (all pass2 reads of g_sums are done)
    for (int i = t; i < NCLS*DD; i += P2_THREADS) g_sums[i] = 0.f;
    __syncthreads();
    if (t == 0) {
        int last = -1;
        for (int c = 0; c < NCLS; c++) if (vld[c] > 0.f) last = c;
        float tc = 0.f, lvar = 0.f, lreg = 0.f, ldist = 0.f;
        for (int c = 0; c < NCLS; c++) {
            if (vld[c] > 0.f) {
                tc   += 1.f;
                lvar += g_var[c] / fmaxf((float)g_cnt[c], 1.f);
                lreg += sreg[c];
            }
        }
        // faithful buggy double loop: a over all valid, b over valid except
        // the LAST valid class id; includes a == b pairs.
        for (int a = 0; a < NCLS; a++)
            for (int b2 = 0; b2 < NCLS; b2++)
                if (vld[a] > 0.f && vld[b2] > 0.f && b2 != last)
                    ldist += spair[a*NCLS + b2];
        out[0] = lvar/tc + ldist/(tc*(tc - 1.f)) + 0.001f*lreg/tc;  // ALPHA=BETA=1, GAMMA=1e-3
        // reset for next replay (g_cnt is re-accumulated by pass1)
        for (int c = 0; c < NCLS; c++) { g_var[c] = 0.f; g_cnt[c] = 0; }
        g_done2 = 0u;
    }
}

// ---------------------------------------------------------------- launch
extern "C" void kernel_launch(void* const* d_in, const int* in_sizes, int n_in,
                              void* d_out, int out_size) {
    const float* feats  = (const float*)d_in[0];
    const int*   labels = (const int*)d_in[1];
    float* out = (float*)d_out;

    k_pass1<<<P1_BLOCKS, P1_THREADS>>>(feats, labels);
    k_pass2<<<P2_BLOCKS, P2_THREADS>>>(feats, out);
}

// round 16
// speedup vs baseline: 1.0818x; 1.0818x over previous
#include <cuda_runtime.h>
#include <math.h>

#define NCLS 19
#define DD   128
#define HWP  65536          // H*W
#define BB   8
#define NPIX (BB*HWP)       // 524288

#define P1_BLOCKS  592              // 4 x 148 SMs, single wave
#define P1_THREADS 288              // 8 MMA warps (dims) + 1 label warp
#define P1_CHUNK   128              // pixels per chunk (8 ksteps)
#define P1_NCHUNK  (NPIX/P1_CHUNK)  // 4096

#define P2_THREADS 256
#define P2_PXB     512              // pixels per block
#define P2_BLOCKS  (NPIX/P2_PXB)    // 1024
#define P2_STAGES  32               // 4 planes per stage
#define P2_STAGE_FLTS (4*P2_PXB)    // 2048 floats = 8KB per stage

// ---- static scratch (no allocations allowed; zero-init at load) ----
__device__ float          g_sums[NCLS*DD];
__device__ int            g_cnt[NCLS];
__device__ float          g_var[NCLS];
__device__ unsigned int   g_done2;
__device__ unsigned char  g_labs[NPIX];

// ---------------------------------------------------------------- pass 1
// Segment-sum as GEMM: D[d][c] = sum_p feats[d][p] * onehot(lab[p]==c).
// Warps 0..7: mma.sync.m16n8k16, A = feats [16 dims x 16 px] bf16 loaded
// straight from global in fragment layout (__ldcs), B = onehot built in
// registers from raw int32 labels, C = fp32 [16 d x 24 cls]; single
// atomic writeout. Warp 8: label histogram + pack (replaces prep kernel).
__global__ void __launch_bounds__(P1_THREADS, 4) k_pass1(const float* __restrict__ feats,
                                                         const int* __restrict__ labels) {
    __shared__ int hist[NCLS];
    int w    = threadIdx.x >> 5;
    int lane = threadIdx.x & 31;

    if (w == 8) {
        // ---------------- label warp: histogram + pack ----------------
        if (lane < NCLS) hist[lane] = 0;
        __syncwarp();
        for (int ch = blockIdx.x; ch < P1_NCHUNK; ch += P1_BLOCKS) {
            int pxg = ch * P1_CHUNK;
            int4 lv = ((const int4*)(labels + pxg))[lane];   // 4 labels/lane
            uchar4 u;
            u.x = (lv.x >= 0 && lv.x < NCLS) ? (unsigned char)lv.x : (unsigned char)255;
            u.y = (lv.y >= 0 && lv.y < NCLS) ? (unsigned char)lv.y : (unsigned char)255;
            u.z = (lv.z >= 0 && lv.z < NCLS) ? (unsigned char)lv.z : (unsigned char)255;
            u.w = (lv.w >= 0 && lv.w < NCLS) ? (unsigned char)lv.w : (unsigned char)255;
            ((uchar4*)(g_labs + pxg))[lane] = u;
            if (u.x < NCLS) atomicAdd(&hist[u.x], 1);
            if (u.y < NCLS) atomicAdd(&hist[u.y], 1);
            if (u.z < NCLS) atomicAdd(&hist[u.z], 1);
            if (u.w < NCLS) atomicAdd(&hist[u.w], 1);
        }
        __syncwarp();
        if (lane < NCLS) atomicAdd(&g_cnt[lane], hist[lane]);
        return;
    }

    // ---------------- MMA warps: segment-sum GEMM ----------------
    int gid  = lane >> 2;            // 0..7
    int ktid = lane & 3;             // 0..3
    int d_lo = w*16 + gid;

    float c0[4] = {0.f,0.f,0.f,0.f};
    float c1[4] = {0.f,0.f,0.f,0.f};
    float c2[4] = {0.f,0.f,0.f,0.f};

    for (int ch = blockIdx.x; ch < P1_NCHUNK; ch += P1_BLOCKS) {
        int pxg = ch * P1_CHUNK;         // plane-aligned: 128 | 65536
        int b   = pxg >> 16;
        int po  = pxg & 65535;
        const float* rowA = feats + ((size_t)b*DD + d_lo    ) * HWP + po;
        const float* rowB = feats + ((size_t)b*DD + d_lo + 8) * HWP + po;
        const int*   labp = labels + pxg;

        #pragma unroll 2
        for (int ks = 0; ks < P1_CHUNK/16; ks++) {
            int p0 = ks*16 + 2*ktid;     // thread's k-anchor within the 16-px tile
            float2 fa0 = __ldcs((const float2*)(rowA + p0));        // A[gid][k0,k0+1]
            float2 fa1 = __ldcs((const float2*)(rowB + p0));        // A[gid+8][k0,k0+1]
            float2 fa2 = __ldcs((const float2*)(rowA + p0 + 8));    // A[gid][k0+8,k0+9]
            float2 fa3 = __ldcs((const float2*)(rowB + p0 + 8));    // A[gid+8][k0+8,k0+9]
            unsigned a0, a1, a2, a3;
            asm("cvt.rn.bf16x2.f32 %0, %1, %2;" : "=r"(a0) : "f"(fa0.y), "f"(fa0.x));
            asm("cvt.rn.bf16x2.f32 %0, %1, %2;" : "=r"(a1) : "f"(fa1.y), "f"(fa1.x));
            asm("cvt.rn.bf16x2.f32 %0, %1, %2;" : "=r"(a2) : "f"(fa2.y), "f"(fa2.x));
            asm("cvt.rn.bf16x2.f32 %0, %1, %2;" : "=r"(a3) : "f"(fa3.y), "f"(fa3.x));

            int2 L01 = *(const int2*)(labp + p0);       // L1/L2 hit (8 warps share)
            int2 L89 = *(const int2*)(labp + p0 + 8);
            int l0 = L01.x, l1 = L01.y;
            int l8 = L89.x, l9 = L89.y;

            {   int cls = gid;                       // tile 0: classes 0..7
                unsigned b0 = (l0==cls ? 0x3F80u : 0u) | (l1==cls ? 0x3F800000u : 0u);
                unsigned b1 = (l8==cls ? 0x3F80u : 0u) | (l9==cls ? 0x3F800000u : 0u);
                asm("mma.sync.aligned.m16n8k16.row.col.f32.bf16.bf16.f32 "
                    "{%0,%1,%2,%3}, {%4,%5,%6,%7}, {%8,%9}, {%0,%1,%2,%3};"
                    : "+f"(c0[0]), "+f"(c0[1]), "+f"(c0[2]), "+f"(c0[3])
                    : "r"(a0), "r"(a1), "r"(a2), "r"(a3), "r"(b0), "r"(b1));
            }
            {   int cls = gid + 8;                   // tile 1: classes 8..15
                unsigned b0 = (l0==cls ? 0x3F80u : 0u) | (l1==cls ? 0x3F800000u : 0u);
                unsigned b1 = (l8==cls ? 0x3F80u : 0u) | (l9==cls ? 0x3F800000u : 0u);
                asm("mma.sync.aligned.m16n8k16.row.col.f32.bf16.bf16.f32 "
                    "{%0,%1,%2,%3}, {%4,%5,%6,%7}, {%8,%9}, {%0,%1,%2,%3};"
                    : "+f"(c1[0]), "+f"(c1[1]), "+f"(c1[2]), "+f"(c1[3])
                    : "r"(a0), "r"(a1), "r"(a2), "r"(a3), "r"(b0), "r"(b1));
            }
            {   int cls = gid + 16;                  // tile 2: classes 16..23
                unsigned b0 = (l0==cls ? 0x3F80u : 0u) | (l1==cls ? 0x3F800000u : 0u);
                unsigned b1 = (l8==cls ? 0x3F80u : 0u) | (l9==cls ? 0x3F800000u : 0u);
                asm("mma.sync.aligned.m16n8k16.row.col.f32.bf16.bf16.f32 "
                    "{%0,%1,%2,%3}, {%4,%5,%6,%7}, {%8,%9}, {%0,%1,%2,%3};"
                    : "+f"(c2[0]), "+f"(c2[1]), "+f"(c2[2]), "+f"(c2[3])
                    : "r"(a0), "r"(a1), "r"(a2), "r"(a3), "r"(b0), "r"(b1));
            }
        }
    }

    // writeout: C[m][n] -> d = w*16 + m (m = gid, gid+8), cls = 8t + n
    int dA = w*16 + gid, dB = dA + 8;
    {   int n0 = 2*ktid, n1 = n0 + 1;             // tile 0: cls 0..7
        atomicAdd(&g_sums[n0*DD + dA], c0[0]);
        atomicAdd(&g_sums[n1*DD + dA], c0[1]);
        atomicAdd(&g_sums[n0*DD + dB], c0[2]);
        atomicAdd(&g_sums[n1*DD + dB], c0[3]);
    }
    {   int n0 = 8 + 2*ktid, n1 = n0 + 1;         // tile 1: cls 8..15
        atomicAdd(&g_sums[n0*DD + dA], c1[0]);
        atomicAdd(&g_sums[n1*DD + dA], c1[1]);
        atomicAdd(&g_sums[n0*DD + dB], c1[2]);
        atomicAdd(&g_sums[n1*DD + dB], c1[3]);
    }
    {   int n0 = 16 + 2*ktid, n1 = n0 + 1;        // tile 2: cls 16..23 (keep <19)
        if (n0 < NCLS) { atomicAdd(&g_sums[n0*DD + dA], c2[0]);
                         atomicAdd(&g_sums[n0*DD + dB], c2[2]); }
        if (n1 < NCLS) { atomicAdd(&g_sums[n1*DD + dA], c2[1]);
                         atomicAdd(&g_sums[n1*DD + dB], c2[3]); }
    }
}

// ---------------------------------------------------------------- pass 2
// cp.async pipelined reader: block owns 512 contiguous pixels; 32 stages
// of 4 planes x 2KB loaded via cp.async.cg (16B ops, fire-and-forget into
// smem — outstanding bytes bounded by pipeline depth, not registers).
// Double-buffered 8KB stages: 7 blocks/SM x 8KB in flight = 56KB/SM.
// buf is declared FIRST and 16B-aligned (cp.async 16B requires it; R15's
// misaligned-address trap came from buf landing after the 9804B ms array).
// Thread t consumes pixels t and t+256 (stride-1 LDS, conflict-free).
// Means in shared at stride 129. Last block assembles the loss.
__global__ void __launch_bounds__(P2_THREADS, 7) k_pass2(const float* __restrict__ feats,
                                                         float* __restrict__ out) {
    __shared__ __align__(16) float buf[2][P2_STAGE_FLTS];
    __shared__ float ms[NCLS*129];
    __shared__ float vs[NCLS];
    int t = threadIdx.x;
    for (int i = t; i < NCLS*DD; i += P2_THREADS) {
        int c = i >> 7;
        ms[c*129 + (i & 127)] = g_sums[i] / fmaxf((float)g_cnt[c], 1.f);
    }
    if (t < NCLS) vs[t] = 0.f;

    int pxbase = blockIdx.x * P2_PXB;      // plane-aligned (512 | 65536)
    int b      = pxbase >> 16;
    int po     = pxbase & 65535;
    const float* fb = feats + (size_t)b*DD*HWP + po;   // plane d at fb + d*HWP

    int l0 = g_labs[pxbase + t];
    int l1 = g_labs[pxbase + t + 256];
    const float* mr0 = ms + (l0 < NCLS ? l0 : 0)*129;
    const float* mr1 = ms + (l1 < NCLS ? l1 : 0)*129;

    // per-thread cp.async ops: o0 = 2t, o1 = 2t+1; plane = o>>7, 16B chunk = o&127
    int o0 = 2*t, o1 = 2*t + 1;
    int pl0 = o0 >> 7, cw0 = (o0 & 127) * 4;   // float offset within plane row
    int pl1 = o1 >> 7, cw1 = (o1 & 127) * 4;

    unsigned sb0 = (unsigned)__cvta_generic_to_shared(&buf[0][0]);
    unsigned sb1 = (unsigned)__cvta_generic_to_shared(&buf[1][0]);

    // prologue: stage 0 into buf0
    {
        const float* g0 = fb + (size_t)(0 + pl0)*HWP + cw0;
        const float* g1 = fb + (size_t)(0 + pl1)*HWP + cw1;
        asm volatile("cp.async.cg.shared.global [%0], [%1], 16;"
                     :: "r"(sb0 + (unsigned)(pl0*P2_PXB + cw0)*4u), "l"(g0) : "memory");
        asm volatile("cp.async.cg.shared.global [%0], [%1], 16;"
                     :: "r"(sb0 + (unsigned)(pl1*P2_PXB + cw1)*4u), "l"(g1) : "memory");
        asm volatile("cp.async.commit_group;" ::: "memory");
    }

    float acc0 = 0.f, acc1 = 0.f;
    for (int s = 0; s < P2_STAGES; s++) {
        if (s + 1 < P2_STAGES) {
            int d1 = (s + 1) * 4;
            unsigned sb = ((s + 1) & 1) ? sb1 : sb0;
            const float* g0 = fb + (size_t)(d1 + pl0)*HWP + cw0;
            const float* g1 = fb + (size_t)(d1 + pl1)*HWP + cw1;
            asm volatile("cp.async.cg.shared.global [%0], [%1], 16;"
                         :: "r"(sb + (unsigned)(pl0*P2_PXB + cw0)*4u), "l"(g0) : "memory");
            asm volatile("cp.async.cg.shared.global [%0], [%1], 16;"
                         :: "r"(sb + (unsigned)(pl1*P2_PXB + cw1)*4u), "l"(g1) : "memory");
            asm volatile("cp.async.commit_group;" ::: "memory");
            asm volatile("cp.async.wait_group 1;" ::: "memory");
        } else {
            asm volatile("cp.async.wait_group 0;" ::: "memory");
        }
        __syncthreads();                       // stage s fully in smem

        const float* bs = buf[s & 1];
        int d0 = s * 4;
        #pragma unroll
        for (int j = 0; j < 4; j++) {
            float v0 = bs[j*P2_PXB + t];
            float v1 = bs[j*P2_PXB + t + 256];
            float m0 = mr0[d0 + j];
            float m1 = mr1[d0 + j];
            float df0 = v0 - m0; acc0 = fmaf(df0, df0, acc0);
            float df1 = v1 - m1; acc1 = fmaf(df1, df1, acc1);
        }
        __syncthreads();                       // buffer reusable for stage s+2
    }

    if (l0 < NCLS) { float h = fmaxf(sqrtf(acc0) - 0.5f, 0.f); atomicAdd(&vs[l0], h*h); }
    if (l1 < NCLS) { float h = fmaxf(sqrtf(acc1) - 0.5f, 0.f); atomicAdd(&vs[l1], h*h); }
    __syncthreads();
    if (t < NCLS) atomicAdd(&g_var[t], vs[t]);

    // ---- last-arriving block: final loss assembly + scratch reset ----
    __threadfence();
    __shared__ bool isLast;
    if (t == 0) isLast = (atomicAdd(&g_done2, 1u) == P2_BLOCKS - 1);
    __syncthreads();
    if (!isLast) return;

    __shared__ float vld[NCLS];
    __shared__ float sreg[NCLS];
    __shared__ float spair[NCLS*NCLS];
    if (t < NCLS) {
        vld[t] = (g_cnt[t] > 100) ? 1.f : 0.f;   // MAX_VIEWS = 100, strict >
        float s = 0.f;
        #pragma unroll 16
        for (int d = 0; d < DD; d++) { float m = ms[t*129 + d]; s = fmaf(m, m, s); }
        sreg[t] = (s > 0.f) ? sqrtf(s) : 0.f;
    }
    for (int idx = t; idx < NCLS*NCLS; idx += P2_THREADS) {
        int a = idx / NCLS, b2 = idx % NCLS;
        float s = 0.f;
        #pragma unroll 16
        for (int d = 0; d < DD; d++) {
            float diff = ms[a*129 + d] - ms[b2*129 + d];
            s = fmaf(diff, diff, s);
        }
        float pdn = (s > 0.f) ? sqrtf(s) : 0.f;
        float hd  = fmaxf(2.f*1.5f - pdn, 0.f);   // 2*DELTA_D
        spair[idx] = hd*hd;
    }
    // reset g_sums for next replay (all pass2 reads of g_sums are done)
    for (int i = t; i < NCLS*DD; i += P2_THREADS) g_sums[i] = 0.f;
    __syncthreads();
    if (t == 0) {
        int last = -1;
        for (int c = 0; c < NCLS; c++) if (vld[c] > 0.f) last = c;
        float tc = 0.f, lvar = 0.f, lreg = 0.f, ldist = 0.f;
        for (int c = 0; c < NCLS; c++) {
            if (vld[c] > 0.f) {
                tc   += 1.f;
                lvar += g_var[c] / fmaxf((float)g_cnt[c], 1.f);
                lreg += sreg[c];
            }
        }
        // faithful buggy double loop: a over all valid, b over valid except
        // the LAST valid class id; includes a == b pairs.
        for (int a = 0; a < NCLS; a++)
            for (int b2 = 0; b2 < NCLS; b2++)
                if (vld[a] > 0.f && vld[b2] > 0.f && b2 != last)
                    ldist += spair[a*NCLS + b2];
        out[0] = lvar/tc + ldist/(tc*(tc - 1.f)) + 0.001f*lreg/tc;  // ALPHA=BETA=1, GAMMA=1e-3
        // reset for next replay (g_cnt is re-accumulated by pass1)
        for (int c = 0; c < NCLS; c++) { g_var[c] = 0.f; g_cnt[c] = 0; }
        g_done2 = 0u;
    }
}

// ---------------------------------------------------------------- launch
extern "C" void kernel_launch(void* const* d_in, const int* in_sizes, int n_in,
                              void* d_out, int out_size) {
    const float* feats  = (const float*)d_in[0];
    const int*   labels = (const int*)d_in[1];
    float* out = (float*)d_out;

    k_pass1<<<P1_BLOCKS, P1_THREADS>>>(feats, labels);
    k_pass2<<<P2_BLOCKS, P2_THREADS>>>(feats, out);
}